// round 2
// baseline (speedup 1.0000x reference)
#include <cuda_runtime.h>
#include <math.h>

#define BB 4
#define CC 64
#define NN 4096
#define RR 16
#define QT 64
#define MT 128
#define NCH (NN/MT)

// scratch (no allocations allowed)
__device__ float g_Q[BB*NN*RR];
__device__ float g_K[BB*NN*RR];
__device__ float g_V[BB*NN*RR];
__device__ float g_A[BB*NN*RR];   // attention output [b][n][r]
__device__ float g_O[BB*CC*NN];   // proj + residual
__device__ double g_s1[BB];
__device__ double g_s2[BB];

__global__ void zero_kernel() {
    int t = threadIdx.x;
    if (t < BB) { g_s1[t] = 0.0; g_s2[t] = 0.0; }
}

// ---------------------------------------------------------------------------
// QKV projection: q = Wq x + bq (from x), k/v from y. Outputs [b][n][16].
// grid (NN/128, BB), 128 threads.
// ---------------------------------------------------------------------------
__global__ void qkv_kernel(const float* __restrict__ x, const float* __restrict__ y,
                           const float* __restrict__ Wq, const float* __restrict__ bq,
                           const float* __restrict__ Wk, const float* __restrict__ bk,
                           const float* __restrict__ Wv, const float* __restrict__ bv) {
    __shared__ float sW[3*RR*CC];
    __shared__ float sb[3*RR];
    int t = threadIdx.x;
    for (int i = t; i < RR*CC; i += 128) {
        sW[i]           = Wq[i];
        sW[RR*CC + i]   = Wk[i];
        sW[2*RR*CC + i] = Wv[i];
    }
    if (t < RR) { sb[t] = bq[t]; sb[RR+t] = bk[t]; sb[2*RR+t] = bv[t]; }
    __syncthreads();

    int b = blockIdx.y;
    int n = blockIdx.x * 128 + t;
    const float* xp = x + (size_t)b*CC*NN + n;
    const float* yp = y + (size_t)b*CC*NN + n;

    float aq[RR], ak[RR], av[RR];
#pragma unroll
    for (int r = 0; r < RR; r++) { aq[r]=sb[r]; ak[r]=sb[RR+r]; av[r]=sb[2*RR+r]; }

#pragma unroll 4
    for (int c = 0; c < CC; c++) {
        float xv = xp[(size_t)c*NN];
        float yv = yp[(size_t)c*NN];
#pragma unroll
        for (int r = 0; r < RR; r++) {
            aq[r] += sW[r*CC + c] * xv;
            ak[r] += sW[RR*CC + r*CC + c] * yv;
            av[r] += sW[2*RR*CC + r*CC + c] * yv;
        }
    }
    size_t base = (size_t)(b*NN + n) * RR;
    float4* Qo = (float4*)(g_Q + base);
    float4* Ko = (float4*)(g_K + base);
    float4* Vo = (float4*)(g_V + base);
#pragma unroll
    for (int j = 0; j < 4; j++) {
        Qo[j] = make_float4(aq[4*j], aq[4*j+1], aq[4*j+2], aq[4*j+3]);
        Ko[j] = make_float4(ak[4*j], ak[4*j+1], ak[4*j+2], ak[4*j+3]);
        Vo[j] = make_float4(av[4*j], av[4*j+1], av[4*j+2], av[4*j+3]);
    }
}

// ---------------------------------------------------------------------------
// Flash attention, fp32. grid (NN/QT, BB) = (64,4), 256 threads.
// Thread (ty=t/16, tx=t%16): 4 queries (ty*4..+3) x 8 keys (m = 32j + 2tx + e).
// ---------------------------------------------------------------------------
__global__ void __launch_bounds__(256, 2) attn_kernel() {
    __shared__ float sQ[RR*QT];      // [r][q]
    __shared__ float sK[RR*MT];      // [r][m]
    __shared__ float sV[RR*MT];      // [r][m]
    __shared__ float sOut[QT*RR];    // staging for coalesced store

    int t  = threadIdx.x;
    int tx = t & 15;
    int ty = t >> 4;
    int b  = blockIdx.y;
    int q0 = blockIdx.x * QT;

    // load Q tile: thread -> q = t/4, 4 r-values
    {
        int q  = t >> 2;
        int rg = (t & 3) * 4;
        float4 qv = *(const float4*)(g_Q + (size_t)(b*NN + q0 + q)*RR + rg);
        sQ[(rg+0)*QT + q] = qv.x;
        sQ[(rg+1)*QT + q] = qv.y;
        sQ[(rg+2)*QT + q] = qv.z;
        sQ[(rg+3)*QT + q] = qv.w;
    }

    float mr[4], lr[4];
    float acc[4][RR];
#pragma unroll
    for (int i = 0; i < 4; i++) {
        mr[i] = -INFINITY; lr[i] = 0.f;
#pragma unroll
        for (int r = 0; r < RR; r++) acc[i][r] = 0.f;
    }

    int half = t >> 7;       // 0 -> K, 1 -> V
    int mload = t & 127;

    for (int ch = 0; ch < NCH; ch++) {
        __syncthreads();  // prior chunk compute done
        // load K/V chunk [128 m][16 r] -> smem [r][m]
        {
            const float* src = half ? g_V : g_K;
            float* dst = half ? sV : sK;
            const float4* p = (const float4*)(src + (size_t)(b*NN + ch*MT + mload)*RR);
            float4 a0 = p[0], a1 = p[1], a2 = p[2], a3 = p[3];
            dst[ 0*MT+mload]=a0.x; dst[ 1*MT+mload]=a0.y; dst[ 2*MT+mload]=a0.z; dst[ 3*MT+mload]=a0.w;
            dst[ 4*MT+mload]=a1.x; dst[ 5*MT+mload]=a1.y; dst[ 6*MT+mload]=a1.z; dst[ 7*MT+mload]=a1.w;
            dst[ 8*MT+mload]=a2.x; dst[ 9*MT+mload]=a2.y; dst[10*MT+mload]=a2.z; dst[11*MT+mload]=a2.w;
            dst[12*MT+mload]=a3.x; dst[13*MT+mload]=a3.y; dst[14*MT+mload]=a3.z; dst[15*MT+mload]=a3.w;
        }
        __syncthreads();

        // S = Q K^T for the micro-tile
        float S[4][8];
#pragma unroll
        for (int i = 0; i < 4; i++)
#pragma unroll
            for (int jj = 0; jj < 8; jj++) S[i][jj] = 0.f;

#pragma unroll
        for (int r = 0; r < RR; r++) {
            float4 qv = *(const float4*)&sQ[r*QT + ty*4];
#pragma unroll
            for (int j = 0; j < 4; j++) {
                float2 kv = *(const float2*)&sK[r*MT + 32*j + 2*tx];
                S[0][2*j]   += qv.x * kv.x;  S[0][2*j+1] += qv.x * kv.y;
                S[1][2*j]   += qv.y * kv.x;  S[1][2*j+1] += qv.y * kv.y;
                S[2][2*j]   += qv.z * kv.x;  S[2][2*j+1] += qv.z * kv.y;
                S[3][2*j]   += qv.w * kv.x;  S[3][2*j+1] += qv.w * kv.y;
            }
        }

        // online softmax update
#pragma unroll
        for (int i = 0; i < 4; i++) {
            float mx = S[i][0];
#pragma unroll
            for (int jj = 1; jj < 8; jj++) mx = fmaxf(mx, S[i][jj]);
            mx = fmaxf(mx, __shfl_xor_sync(0xffffffffu, mx, 1));
            mx = fmaxf(mx, __shfl_xor_sync(0xffffffffu, mx, 2));
            mx = fmaxf(mx, __shfl_xor_sync(0xffffffffu, mx, 4));
            mx = fmaxf(mx, __shfl_xor_sync(0xffffffffu, mx, 8));
            float mnew = fmaxf(mr[i], mx);
            float sc = __expf(mr[i] - mnew);
            mr[i] = mnew;
            float rs = 0.f;
#pragma unroll
            for (int jj = 0; jj < 8; jj++) {
                S[i][jj] = __expf(S[i][jj] - mnew);
                rs += S[i][jj];
            }
            rs += __shfl_xor_sync(0xffffffffu, rs, 1);
            rs += __shfl_xor_sync(0xffffffffu, rs, 2);
            rs += __shfl_xor_sync(0xffffffffu, rs, 4);
            rs += __shfl_xor_sync(0xffffffffu, rs, 8);
            lr[i] = lr[i] * sc + rs;
#pragma unroll
            for (int r = 0; r < RR; r++) acc[i][r] *= sc;
        }

        // acc += P * V
#pragma unroll
        for (int r = 0; r < RR; r++) {
#pragma unroll
            for (int j = 0; j < 4; j++) {
                float2 vv = *(const float2*)&sV[r*MT + 32*j + 2*tx];
                acc[0][r] += S[0][2*j]*vv.x + S[0][2*j+1]*vv.y;
                acc[1][r] += S[1][2*j]*vv.x + S[1][2*j+1]*vv.y;
                acc[2][r] += S[2][2*j]*vv.x + S[2][2*j+1]*vv.y;
                acc[3][r] += S[3][2*j]*vv.x + S[3][2*j+1]*vv.y;
            }
        }
    }

    // reduce partial accumulators across the 16 tx lanes
#pragma unroll
    for (int i = 0; i < 4; i++)
#pragma unroll
        for (int r = 0; r < RR; r++) {
            float v = acc[i][r];
            v += __shfl_xor_sync(0xffffffffu, v, 1);
            v += __shfl_xor_sync(0xffffffffu, v, 2);
            v += __shfl_xor_sync(0xffffffffu, v, 4);
            v += __shfl_xor_sync(0xffffffffu, v, 8);
            acc[i][r] = v;
        }

    if (tx == 0) {
#pragma unroll
        for (int i = 0; i < 4; i++) {
            float inv = 1.f / lr[i];
#pragma unroll
            for (int r = 0; r < RR; r++)
                sOut[(ty*4 + i)*RR + r] = acc[i][r] * inv;
        }
    }
    __syncthreads();
    {
        float4 o = *(const float4*)&sOut[t*4];
        *(float4*)(g_A + (size_t)(b*NN + q0)*RR + t*4) = o;
    }
}

// ---------------------------------------------------------------------------
// Final projection + bias + residual, write g_O, accumulate sum/sumsq.
// grid (NN/128, BB), 128 threads.
// ---------------------------------------------------------------------------
__global__ void proj_kernel(const float* __restrict__ x,
                            const float* __restrict__ Wf, const float* __restrict__ bf) {
    __shared__ float sW[CC*RR];
    __shared__ float sb[CC];
    int t = threadIdx.x;
    for (int i = t; i < CC*RR; i += 128) sW[i] = Wf[i];
    if (t < CC) sb[t] = bf[t];
    __syncthreads();

    int b = blockIdx.y;
    int n = blockIdx.x * 128 + t;

    float a[RR];
    const float4* ap = (const float4*)(g_A + (size_t)(b*NN + n)*RR);
#pragma unroll
    for (int j = 0; j < 4; j++) {
        float4 v = ap[j];
        a[4*j] = v.x; a[4*j+1] = v.y; a[4*j+2] = v.z; a[4*j+3] = v.w;
    }

    float s1 = 0.f, s2 = 0.f;
    const float* xp = x + (size_t)b*CC*NN + n;
    float* op = g_O + (size_t)b*CC*NN + n;
#pragma unroll 4
    for (int c = 0; c < CC; c++) {
        float f = sb[c];
#pragma unroll
        for (int r = 0; r < RR; r++) f += sW[c*RR + r] * a[r];
        float val = f + xp[(size_t)c*NN];
        op[(size_t)c*NN] = val;
        s1 += val;
        s2 += val * val;
    }

    // warp reduce, then per-warp atomic
#pragma unroll
    for (int d = 16; d >= 1; d >>= 1) {
        s1 += __shfl_xor_sync(0xffffffffu, s1, d);
        s2 += __shfl_xor_sync(0xffffffffu, s2, d);
    }
    if ((t & 31) == 0) {
        atomicAdd(&g_s1[b], (double)s1);
        atomicAdd(&g_s2[b], (double)s2);
    }
}

// ---------------------------------------------------------------------------
// LayerNorm apply. grid-stride over B*C*N.
// ---------------------------------------------------------------------------
__global__ void norm_kernel(const float* __restrict__ ln_w,
                            const float* __restrict__ ln_b,
                            float* __restrict__ out) {
    const float invn = 1.0f / (float)(CC*NN);
    int idx = blockIdx.x * blockDim.x + threadIdx.x;
    int total = BB*CC*NN;
    for (; idx < total; idx += gridDim.x * blockDim.x) {
        int b  = idx >> 18;          // CC*NN = 262144 = 2^18
        int cn = idx & (CC*NN - 1);
        float mean = (float)g_s1[b] * invn;
        float var  = (float)g_s2[b] * invn - mean * mean;
        float rstd = rsqrtf(var + 1e-5f);
        float v = g_O[idx];
        out[idx] = (v - mean) * rstd * ln_w[cn] + ln_b[cn];
    }
}

extern "C" void kernel_launch(void* const* d_in, const int* in_sizes, int n_in,
                              void* d_out, int out_size) {
    const float* x    = (const float*)d_in[0];
    const float* y    = (const float*)d_in[1];
    const float* Wq   = (const float*)d_in[2];
    const float* bq   = (const float*)d_in[3];
    const float* Wk   = (const float*)d_in[4];
    const float* bk   = (const float*)d_in[5];
    const float* Wv   = (const float*)d_in[6];
    const float* bv   = (const float*)d_in[7];
    const float* Wf   = (const float*)d_in[8];
    const float* bf   = (const float*)d_in[9];
    const float* ln_w = (const float*)d_in[10];
    const float* ln_b = (const float*)d_in[11];
    float* out = (float*)d_out;

    zero_kernel<<<1, 32>>>();
    qkv_kernel<<<dim3(NN/128, BB), 128>>>(x, y, Wq, bq, Wk, bk, Wv, bv);
    attn_kernel<<<dim3(NN/QT, BB), 256>>>();
    proj_kernel<<<dim3(NN/128, BB), 128>>>(x, Wf, bf);
    norm_kernel<<<dim3(512), 256>>>(ln_w, ln_b, out);
}